// round 4
// baseline (speedup 1.0000x reference)
#include <cuda_runtime.h>
#include <cuda_bf16.h>
#include <cstdint>

// Problem constants
#define Mv 8192
#define Nv 8192
#define Cv 80

#define ZCH 16      // row-chunk slots per class in write kernel
#define ROWS_PER_CHUNK 8

// Scratch (no allocation allowed in kernel_launch)
__device__ float g_base[Nv];
__device__ int   g_perm[Mv];
__device__ int   g_off[Cv + 1];

// Fast softplus: log(1+e^x) = max(x,0) + log(1 + e^{-|x|})
__device__ __forceinline__ float softplus_fast(float x) {
    float e = __expf(-fabsf(x));
    return fmaxf(x, 0.0f) + __logf(1.0f + e);
}

// Kernel 1: base[n] = sum_c softplus(pre_cls[n, c])
// grid 128 blocks x 64 threads -> thread-per-row, full SM coverage
__global__ void __launch_bounds__(64) base_kernel(const float* __restrict__ pc) {
    int n = blockIdx.x * 64 + threadIdx.x;
    const float4* row = reinterpret_cast<const float4*>(pc + (size_t)n * Cv);
    float s = 0.0f;
#pragma unroll
    for (int i = 0; i < Cv / 4; i++) {
        float4 v = row[i];
        s += softplus_fast(v.x) + softplus_fast(v.y) +
             softplus_fast(v.z) + softplus_fast(v.w);
    }
    g_base[n] = s;
}

// Kernel 2: counting sort of rows m by class g[m] -> g_perm, g_off
__global__ void group_kernel(const int* __restrict__ g) {
    __shared__ int cnt[Cv];
    __shared__ int offs[Cv + 1];
    int tid = threadIdx.x;
    if (tid < Cv) cnt[tid] = 0;
    __syncthreads();
    for (int m = tid; m < Mv; m += blockDim.x)
        atomicAdd(&cnt[g[m]], 1);
    __syncthreads();
    if (tid == 0) {
        int acc = 0;
        for (int c = 0; c < Cv; c++) { offs[c] = acc; acc += cnt[c]; }
        offs[Cv] = acc;
    }
    __syncthreads();
    if (tid <= Cv) g_off[tid] = offs[tid];
    if (tid < Cv)  cnt[tid] = offs[tid];   // reuse as cursor
    __syncthreads();
    for (int m = tid; m < Mv; m += blockDim.x) {
        int pos = atomicAdd(&cnt[g[m]], 1);
        g_perm[pos] = m;
    }
}

// Kernel 3: grid = (Nv/1024 segs, Cv classes, ZCH chunks), block = 256.
// Each block computes its 1024-column slice of (base - pc[:,c]) once into
// registers, then streams it to its interleaved subset of rows of class c.
__global__ void __launch_bounds__(256) write_kernel(const float* __restrict__ pc,
                                                    float* __restrict__ out) {
    const int c  = blockIdx.y;
    const int i0 = g_off[c];
    const int i1 = g_off[c + 1];
    const int zi = blockIdx.z;

    const int start = i0 + zi * ROWS_PER_CHUNK;
    if (start >= i1) return;   // empty chunk slot: exit before any data loads

    const int n0 = (blockIdx.x * 256 + threadIdx.x) * 4;

    float4 b = *reinterpret_cast<const float4*>(g_base + n0);
    float4 v;
    v.x = b.x - __ldg(&pc[(size_t)(n0 + 0) * Cv + c]);
    v.y = b.y - __ldg(&pc[(size_t)(n0 + 1) * Cv + c]);
    v.z = b.z - __ldg(&pc[(size_t)(n0 + 2) * Cv + c]);
    v.w = b.w - __ldg(&pc[(size_t)(n0 + 3) * Cv + c]);

    float4* out4 = reinterpret_cast<float4*>(out);
    const size_t col = (size_t)(n0 >> 2);

    // Grid-stride over this class's rows: chunk zi takes rows
    // [i0 + zi*8, +8), then jumps ZCH*8. Correct for any class-count skew.
    for (int ci = start; ci < i1; ci += ZCH * ROWS_PER_CHUNK) {
        int end = min(ci + ROWS_PER_CHUNK, i1);
#pragma unroll 2
        for (int i = ci; i < end; i++) {
            int m = g_perm[i];                       // broadcast load
            __stcs(&out4[(size_t)m * (Nv / 4) + col], v);  // streaming STG.128
        }
    }
}

extern "C" void kernel_launch(void* const* d_in, const int* in_sizes, int n_in,
                              void* d_out, int out_size) {
    const int*   g;
    const float* pc;
    if (in_sizes[0] == Mv) {
        g  = (const int*)d_in[0];
        pc = (const float*)d_in[1];
    } else {
        g  = (const int*)d_in[1];
        pc = (const float*)d_in[0];
    }
    float* out = (float*)d_out;

    base_kernel<<<Nv / 64, 64>>>(pc);
    group_kernel<<<1, 1024>>>(g);
    dim3 grid(Nv / 1024, Cv, ZCH);
    write_kernel<<<grid, 256>>>(pc, out);
}

// round 5
// speedup vs baseline: 1.3471x; 1.3471x over previous
#include <cuda_runtime.h>
#include <cuda_bf16.h>
#include <cstdint>

// Problem constants
#define Mv 8192
#define Nv 8192
#define Cv 80

#define ZSPLIT 8          // row interleave factor per class in write kernel
#define ROWS_T 64         // rows per vmat block
#define SPAD 81           // smem row stride (odd-ish -> conflict-free column walks)

// Scratch (no allocation allowed in kernel_launch)
__device__ float g_V[Cv][Nv];     // V[c][n] = base[n] - pc[n][c]
__device__ int   g_perm[Mv];
__device__ int   g_off[Cv + 1];

// Kernel 1 (fused): compute base[n] and V[c][n] in one pass.
// grid = Nv/ROWS_T = 128 blocks, 64 threads.
__global__ void __launch_bounds__(64) vmat_kernel(const float* __restrict__ pc) {
    __shared__ float sp[ROWS_T * SPAD];
    const int n0 = blockIdx.x * ROWS_T;
    const int t  = threadIdx.x;

    // Phase A: cooperative, coalesced load of rows [n0, n0+64) into smem.
    // Tile = 64 rows x 80 floats = 1280 float4; 20 per thread, stride-64.
    const float4* src = reinterpret_cast<const float4*>(pc + (size_t)n0 * Cv);
#pragma unroll
    for (int i = 0; i < 20; i++) {
        int q = i * 64 + t;            // float4 index within tile
        float4 v = src[q];             // consecutive across threads -> coalesced
        int row = q / 20, c4 = q % 20;
        float* d = &sp[row * SPAD + c4 * 4];
        d[0] = v.x; d[1] = v.y; d[2] = v.z; d[3] = v.w;
    }
    __syncthreads();

    // Phase B: per-thread row sum of softplus (stride-81 -> conflict-free).
    float s = 0.0f;
#pragma unroll 4
    for (int c = 0; c < Cv; c++) {
        float x = sp[t * SPAD + c];
        s += fmaxf(x, 0.0f) + __logf(1.0f + __expf(-fabsf(x)));
    }

    // Phase C: V[c][n] = base[n] - pc[n][c]; coalesced along n per c.
#pragma unroll 4
    for (int c = 0; c < Cv; c++) {
        g_V[c][n0 + t] = s - sp[t * SPAD + c];
    }
}

// Kernel 2: counting sort of rows m by class g[m] -> g_perm, g_off
__global__ void group_kernel(const int* __restrict__ g) {
    __shared__ int cnt[Cv];
    __shared__ int offs[Cv + 1];
    int tid = threadIdx.x;
    if (tid < Cv) cnt[tid] = 0;
    __syncthreads();
    for (int m = tid; m < Mv; m += blockDim.x)
        atomicAdd(&cnt[g[m]], 1);
    __syncthreads();
    if (tid == 0) {
        int acc = 0;
        for (int c = 0; c < Cv; c++) { offs[c] = acc; acc += cnt[c]; }
        offs[Cv] = acc;
    }
    __syncthreads();
    if (tid <= Cv) g_off[tid] = offs[tid];
    if (tid < Cv)  cnt[tid] = offs[tid];   // reuse as cursor
    __syncthreads();
    for (int m = tid; m < Mv; m += blockDim.x) {
        int pos = atomicAdd(&cnt[g[m]], 1);
        g_perm[pos] = m;
    }
}

// Kernel 3: grid = (Nv/1024, Cv, ZSPLIT), block = 256.
// Setup = one coalesced 4KB read of V[c] slice; then stream the slice to this
// block's interleaved subset of the class's output rows (plain STG.128).
__global__ void __launch_bounds__(256) write_kernel(float* __restrict__ out) {
    const int c  = blockIdx.y;
    const int z  = blockIdx.z;
    const int i0 = g_off[c];
    const int i1 = g_off[c + 1];
    if (i0 + z >= i1) return;          // no rows for this chunk slot

    const int n0 = (blockIdx.x * 256 + threadIdx.x) * 4;
    const float4 v = *reinterpret_cast<const float4*>(&g_V[c][n0]);

    float4* out4 = reinterpret_cast<float4*>(out);
    const size_t col = (size_t)(n0 >> 2);

    // Interleaved grid-stride over the class's rows: balanced for any skew.
    for (int i = i0 + z; i < i1; i += ZSPLIT) {
        int m = g_perm[i];                      // broadcast load
        out4[(size_t)m * (Nv / 4) + col] = v;   // coalesced STG.128
    }
}

extern "C" void kernel_launch(void* const* d_in, const int* in_sizes, int n_in,
                              void* d_out, int out_size) {
    const int*   g;
    const float* pc;
    if (in_sizes[0] == Mv) {
        g  = (const int*)d_in[0];
        pc = (const float*)d_in[1];
    } else {
        g  = (const int*)d_in[1];
        pc = (const float*)d_in[0];
    }
    float* out = (float*)d_out;

    vmat_kernel<<<Nv / ROWS_T, ROWS_T>>>(pc);
    group_kernel<<<1, 1024>>>(g);
    dim3 grid(Nv / 1024, Cv, ZSPLIT);
    write_kernel<<<grid, 256>>>(out);
}

// round 6
// speedup vs baseline: 1.6223x; 1.2043x over previous
#include <cuda_runtime.h>
#include <cuda_bf16.h>
#include <cstdint>

// Problem constants
#define Mv 8192
#define Nv 8192
#define Cv 80

#define ZSPLIT 16         // row interleave factor per class in write kernel
#define ROWS_T 64         // rows per vmat block
#define SPAD 81           // smem row stride -> conflict-free column walks

// Scratch (no allocation allowed in kernel_launch)
__device__ float g_V[Cv][Nv];     // V[c][n] = base[n] - pc[n][c]
__device__ int   g_perm[Mv];
__device__ int   g_off[Cv + 1];

// Fused phase 1: blocks 0..127 compute V; block 128 does the class grouping.
// blockDim = 256.
__global__ void __launch_bounds__(256) phase1_kernel(const float* __restrict__ pc,
                                                     const int* __restrict__ g) {
    if (blockIdx.x < 128) {
        // ---------------- vmat path: 64 rows, 4 threads per row ----------
        __shared__ float sp[ROWS_T * SPAD];       // 20.7 KB tile
        __shared__ float sS[ROWS_T][4];           // partial max-sums
        __shared__ float sP[ROWS_T][4];           // partial products
        __shared__ float sb[ROWS_T];              // base per row

        const int n0 = blockIdx.x * ROWS_T;
        const int t  = threadIdx.x;

        // Load tile (64 rows x 80 floats = 1280 float4), coalesced.
        const float4* src = reinterpret_cast<const float4*>(pc + (size_t)n0 * Cv);
#pragma unroll
        for (int i = 0; i < 5; i++) {
            int q4 = i * 256 + t;
            float4 v = src[q4];
            int row = q4 / 20, c4 = q4 % 20;
            float* d = &sp[row * SPAD + c4 * 4];
            d[0] = v.x; d[1] = v.y; d[2] = v.z; d[3] = v.w;
        }
        __syncthreads();

        // Each thread: 20 classes of one row. S = sum max(x,0); P = prod(1+e^{-|x|}).
        const int r = t & 63;
        const int q = t >> 6;
        float S = 0.0f, P = 1.0f;
#pragma unroll 5
        for (int j = 0; j < 20; j++) {
            float x = sp[r * SPAD + q * 20 + j];
            S += fmaxf(x, 0.0f);
            P *= 1.0f + __expf(-fabsf(x));
        }
        sS[r][q] = S;
        sP[r][q] = P;
        __syncthreads();

        // Rows reduce: base = sum(S) + log(prod(P))  -> one LG2 per row.
        if (t < ROWS_T) {
            float Ssum = sS[t][0] + sS[t][1] + sS[t][2] + sS[t][3];
            float Pprod = (sP[t][0] * sP[t][1]) * (sP[t][2] * sP[t][3]);
            sb[t] = Ssum + __logf(Pprod);
        }
        __syncthreads();

        // V[c][n0+r] = base[r] - x ; 64-float coalesced runs per c.
#pragma unroll 4
        for (int idx = t; idx < Cv * ROWS_T; idx += 256) {
            int c = idx >> 6, rr = idx & 63;
            g_V[c][n0 + rr] = sb[rr] - sp[rr * SPAD + c];
        }
    } else {
        // ---------------- group path: counting sort by class -------------
        __shared__ int cnt[Cv];
        __shared__ int offs[Cv + 1];
        int tid = threadIdx.x;
        if (tid < Cv) cnt[tid] = 0;
        __syncthreads();
        for (int m = tid; m < Mv; m += 256)
            atomicAdd(&cnt[g[m]], 1);
        __syncthreads();
        if (tid == 0) {
            int acc = 0;
            for (int c = 0; c < Cv; c++) { offs[c] = acc; acc += cnt[c]; }
            offs[Cv] = acc;
        }
        __syncthreads();
        if (tid <= Cv) g_off[tid] = offs[tid];
        if (tid < Cv)  cnt[tid] = offs[tid];   // reuse as cursor
        __syncthreads();
        for (int m = tid; m < Mv; m += 256) {
            int pos = atomicAdd(&cnt[g[m]], 1);
            g_perm[pos] = m;
        }
    }
}

// Write kernel: grid = (Nv/1024, Cv, ZSPLIT), block = 256.
// Setup = one coalesced 4KB read of V[c]; stream it to this block's
// interleaved subset of the class's output rows with evict-first stores.
__global__ void __launch_bounds__(256) write_kernel(float* __restrict__ out) {
    const int c  = blockIdx.y;
    const int z  = blockIdx.z;
    const int i0 = g_off[c];
    const int i1 = g_off[c + 1];
    if (i0 + z >= i1) return;

    const int n0 = (blockIdx.x * 256 + threadIdx.x) * 4;
    const float4 v = *reinterpret_cast<const float4*>(&g_V[c][n0]);

    float4* out4 = reinterpret_cast<float4*>(out);
    const size_t col = (size_t)(n0 >> 2);

    for (int i = i0 + z; i < i1; i += ZSPLIT) {
        int m = g_perm[i];                              // broadcast load
        __stcs(&out4[(size_t)m * (Nv / 4) + col], v);   // streaming STG.128
    }
}

extern "C" void kernel_launch(void* const* d_in, const int* in_sizes, int n_in,
                              void* d_out, int out_size) {
    const int*   g;
    const float* pc;
    if (in_sizes[0] == Mv) {
        g  = (const int*)d_in[0];
        pc = (const float*)d_in[1];
    } else {
        g  = (const int*)d_in[1];
        pc = (const float*)d_in[0];
    }
    float* out = (float*)d_out;

    phase1_kernel<<<129, 256>>>(pc, g);
    dim3 grid(Nv / 1024, Cv, ZSPLIT);
    write_kernel<<<grid, 256>>>(out);
}